// round 1
// baseline (speedup 1.0000x reference)
#include <cuda_runtime.h>

#define N_COL 256
#define N_ROW 256
#define N_CELLS (N_COL * N_ROW)
#define N_AGENT_PTS (64 * 1001)
#define BATCH 512
#define N_TOTAL (BATCH * N_CELLS)

// Scratch (allocation-free rule: __device__ globals)
__device__ unsigned int g_touched[N_CELLS];
__device__ __align__(16) float g_maskf[N_CELLS];
__device__ float g_scale;

// 1) zero the touched flags (must be re-done every launch: deterministic)
__global__ void k_init() {
    int i = blockIdx.x * blockDim.x + threadIdx.x;
    if (i < N_CELLS) g_touched[i] = 0u;
}

// 2) scatter: each agent sample marks its (rotated) cell if inside the box
__global__ void k_scatter(const float* __restrict__ ax, const float* __restrict__ ay) {
    int i = blockIdx.x * blockDim.x + threadIdx.x;
    if (i >= N_AGENT_PTS) return;
    float fx = ax[i] * (float)N_COL;
    float fy = ay[i] * (float)N_ROW;
    float cx = floorf(fx);
    float cy = floorf(fy);
    float rx = fx - cx;
    float ry = fy - cy;
    bool in_box = (rx >= 0.25f) && (rx <= 0.75f) && (ry >= 0.25f) && (ry <= 0.75f);
    if (in_box) {
        int ix = min(max((int)cx, 0), N_COL - 1);
        int iy = min(max((int)cy, 0), N_ROW - 1);
        // Pre-rotated index: rot90 CCW means out[i,j] = m[j, 255-i]
        // source cell (ix,iy) lands at output k = (255-iy)*256 + ix
        int k = (N_ROW - 1 - iy) * N_COL + ix;
        atomicOr(&g_touched[k], 1u);
    }
}

// 3) count touched cells -> scale = n / (n - count)
__global__ void k_reduce() {
    __shared__ int s[1024];
    int t = threadIdx.x;
    int cnt = 0;
    for (int i = t; i < N_CELLS; i += 1024) cnt += (int)g_touched[i];
    s[t] = cnt;
    __syncthreads();
    for (int o = 512; o > 0; o >>= 1) {
        if (t < o) s[t] += s[t + o];
        __syncthreads();
    }
    if (t == 0) {
        float sum_mask = (float)(N_CELLS - s[0]);
        // reference: scale = 1/(1 - dropout_rate) = n / sum(mask)
        g_scale = (float)N_CELLS / sum_mask;
    }
}

// 4) build pre-scaled float mask (already in rotated layout)
__global__ void k_mask() {
    int i = blockIdx.x * blockDim.x + threadIdx.x;
    if (i < N_CELLS) g_maskf[i] = g_touched[i] ? 0.0f : g_scale;
}

// 5) the big one: out = in * maskf, float4 vectorized. Mask (256 KB) lives in L2.
__global__ void __launch_bounds__(256) k_apply(const float4* __restrict__ in,
                                               float4* __restrict__ out) {
    int i = blockIdx.x * blockDim.x + threadIdx.x;  // one float4 per thread
    int m = i & (N_CELLS / 4 - 1);                  // position within the 65536-wide row
    float4 v = in[i];
    float4 mk = reinterpret_cast<const float4*>(g_maskf)[m];
    v.x *= mk.x;
    v.y *= mk.y;
    v.z *= mk.z;
    v.w *= mk.w;
    out[i] = v;
}

extern "C" void kernel_launch(void* const* d_in, const int* in_sizes, int n_in,
                              void* d_out, int out_size) {
    const float* input = (const float*)d_in[0];
    const float* agents_x = (const float*)d_in[1];
    const float* agents_y = (const float*)d_in[2];
    float* out = (float*)d_out;

    k_init<<<N_CELLS / 256, 256>>>();
    k_scatter<<<(N_AGENT_PTS + 255) / 256, 256>>>(agents_x, agents_y);
    k_reduce<<<1, 1024>>>();
    k_mask<<<N_CELLS / 256, 256>>>();

    int n4 = N_TOTAL / 4;  // 8,388,608 float4s
    k_apply<<<n4 / 256, 256>>>((const float4*)input, (float4*)out);
}

// round 2
// speedup vs baseline: 1.1110x; 1.1110x over previous
#include <cuda_runtime.h>

#define N_COL 256
#define N_ROW 256
#define N_CELLS (N_COL * N_ROW)
#define N_WORDS (N_CELLS / 32)      // 2048 bitmask words
#define N_AGENT_PTS (64 * 1001)
#define BATCH 512
#define N_TOTAL (BATCH * N_CELLS)

// Scratch: bitmask (2048 words) + touched-cell counter in one array
// (allocation-free rule: __device__ globals)
__device__ unsigned int g_bits[N_WORDS + 1];   // [N_WORDS] = counter

// 1) zero bitmask + counter (8 KB + 4 B) — one small block, launch-bound
__global__ void k_init() {
    int t = threadIdx.x;
    #pragma unroll
    for (int i = t; i < N_WORDS; i += 1024) g_bits[i] = 0u;
    if (t == 0) g_bits[N_WORDS] = 0u;
}

// 2) scatter: mark rotated cell bit; count newly-set cells exactly
__global__ void k_scatter(const float* __restrict__ ax, const float* __restrict__ ay) {
    int i = blockIdx.x * blockDim.x + threadIdx.x;
    if (i >= N_AGENT_PTS) return;
    float fx = ax[i] * (float)N_COL;
    float fy = ay[i] * (float)N_ROW;
    float cx = floorf(fx);
    float cy = floorf(fy);
    float rx = fx - cx;
    float ry = fy - cy;
    bool in_box = (rx >= 0.25f) && (rx <= 0.75f) && (ry >= 0.25f) && (ry <= 0.75f);
    if (in_box) {
        int ix = min(max((int)cx, 0), N_COL - 1);
        int iy = min(max((int)cy, 0), N_ROW - 1);
        // rot90 CCW folded in: source cell (ix,iy) -> output k = (255-iy)*256 + ix
        int k = (N_ROW - 1 - iy) * N_COL + ix;
        unsigned int bit = 1u << (k & 31);
        unsigned int old = atomicOr(&g_bits[k >> 5], bit);
        if (!(old & bit)) atomicAdd(&g_bits[N_WORDS], 1u);
    }
}

// 3) apply: out = in * mask * scale. Bitmask (8 KB) is L2-resident; scale
//    recomputed per-thread from the exact touched count (1 MUFU, hidden).
__global__ void __launch_bounds__(256) k_apply(const float4* __restrict__ in,
                                               float4* __restrict__ out) {
    int i = blockIdx.x * blockDim.x + threadIdx.x;   // one float4 per thread
    unsigned int cnt = g_bits[N_WORDS];
    float scale = (float)N_CELLS / (float)(N_CELLS - cnt);

    int m = i & (N_CELLS / 4 - 1);        // float4 index within the 65536 row
    unsigned int word = g_bits[m >> 3];   // cell base k = m*4; word = k>>5
    unsigned int b = word >> ((m & 7) * 4);  // 4 adjacent bits for these cells

    float4 v = in[i];
    v.x = (b & 1u) ? 0.0f : v.x * scale;
    v.y = (b & 2u) ? 0.0f : v.y * scale;
    v.z = (b & 4u) ? 0.0f : v.z * scale;
    v.w = (b & 8u) ? 0.0f : v.w * scale;
    out[i] = v;
}

extern "C" void kernel_launch(void* const* d_in, const int* in_sizes, int n_in,
                              void* d_out, int out_size) {
    const float* input = (const float*)d_in[0];
    const float* agents_x = (const float*)d_in[1];
    const float* agents_y = (const float*)d_in[2];
    float* out = (float*)d_out;

    k_init<<<1, 1024>>>();
    k_scatter<<<(N_AGENT_PTS + 255) / 256, 256>>>(agents_x, agents_y);

    int n4 = N_TOTAL / 4;  // 8,388,608 float4s
    k_apply<<<n4 / 256, 256>>>((const float4*)input, (float4*)out);
}